// round 3
// baseline (speedup 1.0000x reference)
#include <cuda_runtime.h>
#include <math.h>

#define BB 32
#define NN 128
#define FF 10
#define DD 64
#define TK 20
#define EX 25
#define BNN 4096           // B*N
#define G2 8192            // 2*BN
#define NE (BNN*EX)        // 102400 edges in layer 2

// ---------------- scratch (device globals: allocation-free) ----------------
__device__ float d_h[BNN*DD];
__device__ float d_si[BNN], d_sj[BNN];
__device__ float d_ei[NN], d_ej[NN], d_invn1[NN];
__device__ int   d_topi1[NN*TK];
__device__ float d_topv1[NN*TK];
__device__ float d_agg[BNN*DD];
__device__ float d_scale1[DD], d_shift1[DD];
__device__ float d_g[G2*DD];        // rows 0..BN-1 = gcn, BN..2BN-1 = ef
__device__ float d_gn[G2*DD];       // row-normalized g
__device__ float d_h2[BNN*DD];
__device__ float d_hi2[BNN], d_hj2[BNN];
__device__ float d_S[(size_t)BNN*G2];   // 128 MB cosine-score matrix
__device__ int   d_topi2[BNN*EX];
__device__ float d_topv2[BNN*EX];
__device__ unsigned d_segmax[BNN];
__device__ float d_segsum[BNN];
__device__ float d_sc2[NE];
__device__ float d_ev[NE];
__device__ float d_agg2[BNN*DD];
__device__ float d_x3[BNN*DD];
__device__ float d_scale2[DD], d_shift2[DD];

// ---------------- helpers ----------------
__device__ __forceinline__ float lrelu(float x){ return x >= 0.f ? x : 0.2f*x; }
// order-preserving float->uint encoding for atomicMax
__device__ __forceinline__ unsigned fenc(float v){
    unsigned u = __float_as_uint(v);
    return (u & 0x80000000u) ? ~u : (u | 0x80000000u);
}
__device__ __forceinline__ float fdec(unsigned k){
    return (k & 0x80000000u) ? __uint_as_float(k ^ 0x80000000u)
                             : __uint_as_float(~k);
}

// ---------------- K0: zero/init scratch that gets accumulated ----------------
__global__ void k_zero(){
    int idx = blockIdx.x*256 + threadIdx.x;      // 0..262143
    d_agg2[idx] = 0.f;
    d_g[BNN*DD + idx] = 0.f;                     // ef region (atomic accum)
    if(idx < BNN){ d_segsum[idx] = 0.f; d_segmax[idx] = 0x007FFFFFu; } // enc(-inf)
}

// ---------------- K1: emb norms + embedding parts of attention keys ----------
__global__ void k_embprep(const float* __restrict__ emb,
                          const float* __restrict__ ai1,
                          const float* __restrict__ aj1){
    int n = blockIdx.x, t = threadIdx.x;
    float e  = emb[n*DD + t];
    float ss = e*e, vi = e*ai1[DD+t], vj = e*aj1[DD+t];
    __shared__ float sb[6];
    #pragma unroll
    for(int o=16;o>0;o>>=1){
        ss += __shfl_down_sync(0xffffffffu, ss, o);
        vi += __shfl_down_sync(0xffffffffu, vi, o);
        vj += __shfl_down_sync(0xffffffffu, vj, o);
    }
    if((t&31)==0){ int w=t>>5; sb[w]=ss; sb[2+w]=vi; sb[4+w]=vj; }
    __syncthreads();
    if(t==0){
        float nrm = sqrtf(sb[0]+sb[1]);
        d_invn1[n] = 1.f/fmaxf(nrm, 1e-12f);
        d_ei[n] = sb[2]+sb[3];
        d_ej[n] = sb[4]+sb[5];
    }
}

// ---------------- K2: cosine(emb,emb) + top-20 per node ----------------
__global__ void k_cos1(const float* __restrict__ emb){
    int i = blockIdx.x, t = threadIdx.x;            // 128 threads
    __shared__ float se[DD];
    __shared__ float sc[NN];
    __shared__ float rv[NN];
    __shared__ int   ridx[NN];
    if(t < DD) se[t] = emb[i*DD + t];
    __syncthreads();
    float dp = 0.f;
    #pragma unroll
    for(int d=0; d<DD; d++) dp += se[d]*emb[t*DD + d];
    sc[t] = dp * d_invn1[i] * d_invn1[t];
    __syncthreads();
    for(int it=0; it<TK; it++){
        rv[t] = sc[t]; ridx[t] = t;
        __syncthreads();
        for(int s=64; s>0; s>>=1){
            if(t < s){
                float v2 = rv[t+s]; int i2 = ridx[t+s];
                if(v2 > rv[t] || (v2 == rv[t] && i2 < ridx[t])){ rv[t]=v2; ridx[t]=i2; }
            }
            __syncthreads();
        }
        if(t==0){
            d_topv1[i*TK+it] = rv[0];
            d_topi1[i*TK+it] = ridx[0];
            sc[ridx[0]] = -INFINITY;
        }
        __syncthreads();
    }
}

// ---------------- K3: h = x@W1, si/sj scalars ----------------
__global__ void k_h(const float* __restrict__ data, const float* __restrict__ W1,
                    const float* __restrict__ ai1, const float* __restrict__ aj1){
    int r = blockIdx.x, t = threadIdx.x;
    __shared__ float sx[FF];
    __shared__ float sb[4];
    if(t < FF) sx[t] = data[r*FF + t];
    __syncthreads();
    float h = 0.f;
    #pragma unroll
    for(int f=0; f<FF; f++) h += sx[f]*W1[f*DD + t];
    d_h[r*DD + t] = h;
    float vi = h*ai1[t], vj = h*aj1[t];
    #pragma unroll
    for(int o=16;o>0;o>>=1){
        vi += __shfl_down_sync(0xffffffffu, vi, o);
        vj += __shfl_down_sync(0xffffffffu, vj, o);
    }
    if((t&31)==0){ sb[t>>5]=vi; sb[2+(t>>5)]=vj; }
    __syncthreads();
    if(t==0){
        d_si[r] = sb[0]+sb[1] + d_ei[r & (NN-1)];
        d_sj[r] = sb[2]+sb[3] + d_ej[r & (NN-1)];
    }
}

// ---------------- K4: layer-1 edge softmax + aggregation ----------------
__global__ void k_attn1(const float* __restrict__ bias1){
    int r = blockIdx.x, t = threadIdx.x;
    int b = r >> 7, i = r & (NN-1);
    __shared__ int   ssrc[TK];
    __shared__ float sal[TK];
    if(t < TK){
        int sn = d_topi1[i*TK + t];
        int s  = (b<<7) + sn;
        ssrc[t] = s;
        sal[t]  = lrelu(d_si[r] + d_sj[s]) * d_topv1[i*TK + t];
    }
    __syncthreads();
    if(t == 0){
        float m = -INFINITY;
        for(int k=0;k<TK;k++) m = fmaxf(m, sal[k]);
        float e[TK], sum = 0.f;
        for(int k=0;k<TK;k++){ e[k] = expf(sal[k]-m); sum += e[k]; }
        float inv = 1.f/fmaxf(sum, 1e-12f);
        for(int k=0;k<TK;k++) sal[k] = e[k]*inv;
    }
    __syncthreads();
    float a = 0.f;
    #pragma unroll
    for(int k=0;k<TK;k++) a += sal[k]*d_h[ssrc[k]*DD + t];
    d_agg[r*DD + t] = a + bias1[t];
}

// ---------------- batchnorm stats (two-pass, per channel) ----------------
__global__ void k_stats1(const float* __restrict__ gamma, const float* __restrict__ beta){
    int d = blockIdx.x, t = threadIdx.x;            // 256 threads
    __shared__ float sb[8];
    __shared__ float smu;
    float s = 0.f;
    for(int r=t; r<BNN; r+=256) s += d_agg[r*DD + d];
    #pragma unroll
    for(int o=16;o>0;o>>=1) s += __shfl_down_sync(0xffffffffu, s, o);
    if((t&31)==0) sb[t>>5] = s;
    __syncthreads();
    if(t==0){ float tot=0; for(int w=0;w<8;w++) tot+=sb[w]; smu = tot*(1.f/BNN); }
    __syncthreads();
    float mu = smu;
    float q = 0.f;
    for(int r=t; r<BNN; r+=256){ float x = d_agg[r*DD + d] - mu; q += x*x; }
    #pragma unroll
    for(int o=16;o>0;o>>=1) q += __shfl_down_sync(0xffffffffu, q, o);
    if((t&31)==0) sb[t>>5] = q;
    __syncthreads();
    if(t==0){
        float tot=0; for(int w=0;w<8;w++) tot+=sb[w];
        float var = tot*(1.f/BNN);
        float sc  = gamma[d]/sqrtf(var + 1e-5f);
        d_scale1[d] = sc; d_shift1[d] = beta[d] - mu*sc;
    }
}

__global__ void k_bnrelu(){
    int r = blockIdx.x, t = threadIdx.x;
    d_g[r*DD + t] = fmaxf(d_scale1[t]*d_agg[r*DD + t] + d_shift1[t], 0.f);
}

// ---------------- K8: ef = P^T @ gcn (K split across 8 grid slices) ----------
__global__ void k_ef(const float* __restrict__ P){
    __shared__ float As[64][68];   // [i_local][j_local] = P[i][j]
    __shared__ float Bs[64][68];   // [i_local][d]       = gcn[i][d]
    int t = threadIdx.x;
    int j0 = blockIdx.x*64;
    int tx = t & 15, ty = t >> 4;
    float c[4][4] = {};
    for(int cc=0; cc<8; cc++){
        int ib = blockIdx.y*512 + cc*64;
        #pragma unroll
        for(int u=0; u<4; u++){
            int f = t*4 + u; int rr = f>>4; int cq = f&15;
            *(float4*)&As[rr][cq*4] = *(const float4*)&P[(size_t)(ib+rr)*BNN + j0 + cq*4];
            *(float4*)&Bs[rr][cq*4] = *(const float4*)&d_g[(ib+rr)*DD + cq*4];
        }
        __syncthreads();
        #pragma unroll
        for(int k=0; k<64; k++){
            float4 a = *(float4*)&As[k][ty*4];
            float4 b = *(float4*)&Bs[k][tx*4];
            c[0][0]+=a.x*b.x; c[0][1]+=a.x*b.y; c[0][2]+=a.x*b.z; c[0][3]+=a.x*b.w;
            c[1][0]+=a.y*b.x; c[1][1]+=a.y*b.y; c[1][2]+=a.y*b.z; c[1][3]+=a.y*b.w;
            c[2][0]+=a.z*b.x; c[2][1]+=a.z*b.y; c[2][2]+=a.z*b.z; c[2][3]+=a.z*b.w;
            c[3][0]+=a.w*b.x; c[3][1]+=a.w*b.y; c[3][2]+=a.w*b.z; c[3][3]+=a.w*b.w;
        }
        __syncthreads();
    }
    #pragma unroll
    for(int m=0;m<4;m++)
        #pragma unroll
        for(int n=0;n<4;n++)
            atomicAdd(&d_g[(BNN + j0 + ty*4+m)*DD + tx*4+n], c[m][n]);
}

// ---------------- K9: row-normalize g ----------------
__global__ void k_gnorm(){
    int r = blockIdx.x, t = threadIdx.x;
    float v = d_g[r*DD + t];
    float ss = v*v;
    __shared__ float sb[2];
    #pragma unroll
    for(int o=16;o>0;o>>=1) ss += __shfl_down_sync(0xffffffffu, ss, o);
    if((t&31)==0) sb[t>>5] = ss;
    __syncthreads();
    float inv = 1.f/fmaxf(sqrtf(sb[0]+sb[1]), 1e-12f);
    d_gn[r*DD + t] = v*inv;
}

// ---------------- K10: S[4096,8192] = Gn[:BN] @ Gn^T ----------------
__global__ void k_sgemm(){
    __shared__ float As[64][68];   // [k][m]  (transposed on load)
    __shared__ float Bs[64][68];   // [k][n]
    int t = threadIdx.x;
    int j0 = blockIdx.x*64, i0 = blockIdx.y*64;
    #pragma unroll
    for(int u=0; u<4; u++){
        int f = t*4 + u; int rr = f>>4; int cq = f&15;
        float4 va = *(const float4*)&d_gn[(i0+rr)*DD + cq*4];
        As[cq*4+0][rr]=va.x; As[cq*4+1][rr]=va.y; As[cq*4+2][rr]=va.z; As[cq*4+3][rr]=va.w;
        float4 vb = *(const float4*)&d_gn[(j0+rr)*DD + cq*4];
        Bs[cq*4+0][rr]=vb.x; Bs[cq*4+1][rr]=vb.y; Bs[cq*4+2][rr]=vb.z; Bs[cq*4+3][rr]=vb.w;
    }
    __syncthreads();
    int tx = t & 15, ty = t >> 4;
    float c[4][4] = {};
    #pragma unroll
    for(int k=0; k<64; k++){
        float4 a = *(float4*)&As[k][ty*4];
        float4 b = *(float4*)&Bs[k][tx*4];
        c[0][0]+=a.x*b.x; c[0][1]+=a.x*b.y; c[0][2]+=a.x*b.z; c[0][3]+=a.x*b.w;
        c[1][0]+=a.y*b.x; c[1][1]+=a.y*b.y; c[1][2]+=a.y*b.z; c[1][3]+=a.y*b.w;
        c[2][0]+=a.z*b.x; c[2][1]+=a.z*b.y; c[2][2]+=a.z*b.z; c[2][3]+=a.z*b.w;
        c[3][0]+=a.w*b.x; c[3][1]+=a.w*b.y; c[3][2]+=a.w*b.z; c[3][3]+=a.w*b.w;
    }
    #pragma unroll
    for(int m=0;m<4;m++){
        float4 o; o.x=c[m][0]; o.y=c[m][1]; o.z=c[m][2]; o.w=c[m][3];
        *(float4*)&d_S[(size_t)(i0 + ty*4 + m)*G2 + j0 + tx*4] = o;
    }
}

// ---------------- K11: top-25 per row of S (row staged in smem) ----------------
__global__ void k_top25(){
    __shared__ float srow[G2];
    __shared__ float rv[256];
    __shared__ int   ridx[256];
    int r = blockIdx.x, t = threadIdx.x;
    #pragma unroll
    for(int u=0; u<8; u++){
        int q = t + u*256;
        *(float4*)&srow[q*4] = *(const float4*)&d_S[(size_t)r*G2 + q*4];
    }
    __syncthreads();
    for(int it=0; it<EX; it++){
        float bv = -INFINITY; int bi = 0x7fffffff;
        #pragma unroll
        for(int u=0; u<32; u++){
            int idx = t + (u<<8);
            float v = srow[idx];
            if(v > bv || (v == bv && idx < bi)){ bv=v; bi=idx; }
        }
        rv[t] = bv; ridx[t] = bi;
        __syncthreads();
        for(int s=128; s>0; s>>=1){
            if(t < s){
                float v2 = rv[t+s]; int i2 = ridx[t+s];
                if(v2 > rv[t] || (v2 == rv[t] && i2 < ridx[t])){ rv[t]=v2; ridx[t]=i2; }
            }
            __syncthreads();
        }
        if(t==0){
            d_topv2[r*EX+it] = rv[0];
            d_topi2[r*EX+it] = ridx[0];
            srow[ridx[0]] = -INFINITY;
        }
        __syncthreads();
    }
}

// ---------------- K12: h2 = g[:BN] @ W2 + attention scalars ----------------
__global__ void k_h2(const float* __restrict__ W2,
                     const float* __restrict__ ai2, const float* __restrict__ aj2){
    int r = blockIdx.x, t = threadIdx.x;
    __shared__ float sg[DD];
    __shared__ float sb[4];
    sg[t] = d_g[r*DD + t];
    __syncthreads();
    float h = 0.f;
    #pragma unroll
    for(int k=0;k<DD;k++) h += sg[k]*W2[k*DD + t];
    d_h2[r*DD + t] = h;
    float vi = h*ai2[t], vj = h*aj2[t];
    #pragma unroll
    for(int o=16;o>0;o>>=1){
        vi += __shfl_down_sync(0xffffffffu, vi, o);
        vj += __shfl_down_sync(0xffffffffu, vj, o);
    }
    if((t&31)==0){ sb[t>>5]=vi; sb[2+(t>>5)]=vj; }
    __syncthreads();
    if(t==0){ d_hi2[r] = sb[0]+sb[1]; d_hj2[r] = sb[2]+sb[3]; }
}

// ---------------- K13/K14: layer-2 scatter softmax ----------------
__global__ void k_sc2a(){
    int e = blockIdx.x*256 + threadIdx.x;
    int dst = d_topi2[e];
    if(dst < BNN){
        int i = e / EX;
        float sc = lrelu(d_hi2[dst] + d_hj2[i]) * d_topv2[e];
        d_sc2[e] = sc;
        atomicMax(&d_segmax[dst], fenc(sc));
    }
}
__global__ void k_sc2b(){
    int e = blockIdx.x*256 + threadIdx.x;
    int dst = d_topi2[e];
    if(dst < BNN){
        float m  = fdec(d_segmax[dst]);
        float ev = expf(d_sc2[e] - m);
        d_ev[e] = ev;
        atomicAdd(&d_segsum[dst], ev);
    }
}
// K15: scatter aggregation (64 channels per edge)
__global__ void k_agg2(){
    int g = blockIdx.x*256 + threadIdx.x;
    int e = g >> 6, d = g & 63;
    int dst = d_topi2[e];
    if(dst < BNN){
        int src = e / EX;
        float alpha = d_ev[e] / fmaxf(d_segsum[dst], 1e-12f);
        atomicAdd(&d_agg2[dst*DD + d], alpha * d_h2[src*DD + d]);
    }
}

// ---------------- K16: gcn2*emb ----------------
__global__ void k_x3(const float* __restrict__ bias2, const float* __restrict__ emb){
    int r = blockIdx.x, t = threadIdx.x;
    float v = fmaxf(d_agg2[r*DD + t] + bias2[t], 0.f);
    d_x3[r*DD + t] = v * emb[(r & (NN-1))*DD + t];
}

__global__ void k_stats2(const float* __restrict__ gamma, const float* __restrict__ beta){
    int d = blockIdx.x, t = threadIdx.x;
    __shared__ float sb[8];
    __shared__ float smu;
    float s = 0.f;
    for(int r=t; r<BNN; r+=256) s += d_x3[r*DD + d];
    #pragma unroll
    for(int o=16;o>0;o>>=1) s += __shfl_down_sync(0xffffffffu, s, o);
    if((t&31)==0) sb[t>>5] = s;
    __syncthreads();
    if(t==0){ float tot=0; for(int w=0;w<8;w++) tot+=sb[w]; smu = tot*(1.f/BNN); }
    __syncthreads();
    float mu = smu;
    float q = 0.f;
    for(int r=t; r<BNN; r+=256){ float x = d_x3[r*DD + d] - mu; q += x*x; }
    #pragma unroll
    for(int o=16;o>0;o>>=1) q += __shfl_down_sync(0xffffffffu, q, o);
    if((t&31)==0) sb[t>>5] = q;
    __syncthreads();
    if(t==0){
        float tot=0; for(int w=0;w<8;w++) tot+=sb[w];
        float var = tot*(1.f/BNN);
        float sc  = gamma[d]/sqrtf(var + 1e-5f);
        d_scale2[d] = sc; d_shift2[d] = beta[d] - mu*sc;
    }
}

// ---------------- K18: output head ----------------
__global__ void k_out(const float* __restrict__ Wout, const float* __restrict__ bout,
                      float* __restrict__ out){
    int r = blockIdx.x, t = threadIdx.x;
    __shared__ float sb[2];
    float x = fmaxf(d_scale2[t]*d_x3[r*DD + t] + d_shift2[t], 0.f);
    float v = x * Wout[t];
    #pragma unroll
    for(int o=16;o>0;o>>=1) v += __shfl_down_sync(0xffffffffu, v, o);
    if((t&31)==0) sb[t>>5] = v;
    __syncthreads();
    if(t==0) out[r] = sb[0]+sb[1] + bout[0];
}

// ---------------- launch ----------------
extern "C" void kernel_launch(void* const* d_in, const int* in_sizes, int n_in,
                              void* d_out, int out_size){
    (void)in_sizes; (void)n_in; (void)out_size;
    const float* data  = (const float*)d_in[0];
    const float* emb   = (const float*)d_in[1];
    const float* W1    = (const float*)d_in[2];
    const float* ai1   = (const float*)d_in[3];
    const float* aj1   = (const float*)d_in[4];
    const float* bias1 = (const float*)d_in[5];
    const float* bn1g  = (const float*)d_in[6];
    const float* bn1b  = (const float*)d_in[7];
    const float* P     = (const float*)d_in[8];
    const float* W2    = (const float*)d_in[9];
    const float* ai2   = (const float*)d_in[10];
    const float* aj2   = (const float*)d_in[11];
    const float* bias2 = (const float*)d_in[12];
    const float* bnOg  = (const float*)d_in[13];
    const float* bnOb  = (const float*)d_in[14];
    const float* Wout  = (const float*)d_in[15];
    const float* bout  = (const float*)d_in[16];
    float* out = (float*)d_out;

    k_zero   <<<1024, 256>>>();
    k_embprep<<<NN, DD>>>(emb, ai1, aj1);
    k_cos1   <<<NN, NN>>>(emb);
    k_h      <<<BNN, DD>>>(data, W1, ai1, aj1);
    k_attn1  <<<BNN, DD>>>(bias1);
    k_stats1 <<<DD, 256>>>(bn1g, bn1b);
    k_bnrelu <<<BNN, DD>>>();
    k_ef     <<<dim3(64, 8), 256>>>(P);
    k_gnorm  <<<G2, DD>>>();
    k_sgemm  <<<dim3(128, 64), 256>>>();
    k_top25  <<<BNN, 256>>>();
    k_h2     <<<BNN, DD>>>(W2, ai2, aj2);
    k_sc2a   <<<NE/256, 256>>>();
    k_sc2b   <<<NE/256, 256>>>();
    k_agg2   <<<NE*DD/256, 256>>>();
    k_x3     <<<BNN, DD>>>(bias2, emb);
    k_stats2 <<<DD, 256>>>(bnOg, bnOb);
    k_out    <<<BNN, DD>>>(Wout, bout, out);
}